// round 2
// baseline (speedup 1.0000x reference)
#include <cuda_runtime.h>

#define B 16
#define G 5000
#define K 256
#define HID 64
#define STEPS 10
#define NCHUNK 128
#define CHUNK 40      // 128*40 = 5120 >= 5000
#define GT 32         // genes per block in K3

// Scratch (no allocations allowed)
__device__ float g_partial[NCHUNK][B][K];  // 2 MB partial maxes
__device__ float g_Z[B][K];                // propagated module activations
__device__ float g_coff[B];                // cell_emb[cell_idx[b]] . W2 + b2

// ---------------------------------------------------------------------------
// K1: partial max-pool over a gene chunk.
// t_mod_partial[chunk][b][k] = max_{g in chunk} t[b,g] * M[g,k]
// ---------------------------------------------------------------------------
__global__ __launch_bounds__(256) void k1_maxpool(
    const float* __restrict__ t, const float* __restrict__ M)
{
    __shared__ float ts[B][CHUNK];
    const int tid = threadIdx.x;            // 256 threads, tid == k
    const int g0  = blockIdx.x * CHUNK;

    for (int i = tid; i < B * CHUNK; i += 256) {
        int b = i / CHUNK, gg = i % CHUNK;
        int g = g0 + gg;
        ts[b][gg] = (g < G) ? t[b * G + g] : 0.0f;
    }
    __syncthreads();

    float acc[B];
#pragma unroll
    for (int b = 0; b < B; b++) acc[b] = -1e30f;

    for (int gg = 0; gg < CHUNK; gg++) {
        int g = g0 + gg;
        if (g >= G) break;
        float m = M[(size_t)g * K + tid];   // coalesced row of M
#pragma unroll
        for (int b = 0; b < B; b++)
            acc[b] = fmaxf(acc[b], ts[b][gg] * m);
    }

#pragma unroll
    for (int b = 0; b < B; b++)
        g_partial[blockIdx.x][b][tid] = acc[b];
}

// ---------------------------------------------------------------------------
// K2: reduce partial maxes -> t_mod, then 10-step APPNP per batch row.
// One block per b (row-independent recurrence). Also computes c_off[b].
// ---------------------------------------------------------------------------
__global__ __launch_bounds__(256) void k2_appnp(
    const float* __restrict__ A,
    const int*   __restrict__ cell_idx,
    const float* __restrict__ cell_emb,
    const float* __restrict__ W2,
    const float* __restrict__ b2)
{
    const int b = blockIdx.x;
    const int k = threadIdx.x;              // 256 threads, one per module

    __shared__ float tm[K];
    __shared__ float Zs[K];

    float m = -1e30f;
    for (int c = 0; c < NCHUNK; c++)
        m = fmaxf(m, g_partial[c][b][k]);   // coalesced across k
    tm[k] = m;
    Zs[k] = m;
    __syncthreads();

    for (int s = 0; s < STEPS; s++) {
        float acc = 0.0f;
#pragma unroll 8
        for (int j = 0; j < K; j++)
            acc = fmaf(Zs[j], A[j * K + k], acc);  // Zs broadcast, A coalesced
        float zn = 0.9f * acc + 0.1f * tm[k];
        __syncthreads();
        Zs[k] = zn;
        __syncthreads();
    }
    g_Z[b][k] = Zs[k];

    // c_off[b] = sum_j cell_emb[cell_idx[b]][j] * W2[j] + b2
    __shared__ float red[HID];
    if (k < HID) {
        int ci = cell_idx[b];
        red[k] = cell_emb[ci * HID + k] * W2[k];
    }
    __syncthreads();
    if (k < 32) {
        float v = red[k] + red[k + 32];
#pragma unroll
        for (int o = 16; o > 0; o >>= 1)
            v += __shfl_down_sync(0xffffffff, v, o);
        if (k == 0) g_coff[b] = v + b2[0];
    }
}

// ---------------------------------------------------------------------------
// K3: fused z_gene = Z @ M^T, MLP (3->64 relu ->1), cell offset, output.
// Block handles GT genes x all 16 batches. 256 threads = 32 genes x 8 b,
// each thread handles two b values.
// ---------------------------------------------------------------------------
__global__ __launch_bounds__(256) void k3_out(
    const float* __restrict__ ctl,
    const float* __restrict__ t,
    const float* __restrict__ M,
    const float* __restrict__ W1,
    const float* __restrict__ b1,
    const float* __restrict__ W2,
    float* __restrict__ out)
{
    __shared__ float Ms[GT][K + 1];     // padded: conflict-free column reads
    __shared__ float Zsh[B][K + 1];
    __shared__ float W1s[3 * HID];
    __shared__ float b1s[HID], W2s[HID], coffs[B];

    const int tid = threadIdx.x;        // 256
    const int g0  = blockIdx.x * GT;

    for (int i = tid; i < GT * K; i += 256) {
        int gl = i / K, j = i % K;
        int g = g0 + gl;
        Ms[gl][j] = (g < G) ? M[(size_t)g * K + j] : 0.0f;
    }
    for (int i = tid; i < B * K; i += 256)
        Zsh[i / K][i % K] = g_Z[i / K][i % K];
    if (tid < 3 * HID) W1s[tid] = W1[tid];
    if (tid < HID) { b1s[tid] = b1[tid]; W2s[tid] = W2[tid]; }
    if (tid < B)   coffs[tid] = g_coff[tid];
    __syncthreads();

    const int gl = tid & 31;            // lane -> gene
    const int g  = g0 + gl;
    if (g >= G) return;

#pragma unroll
    for (int half = 0; half < 2; half++) {
        const int b = (tid >> 5) + half * 8;

        float z = 0.0f;
#pragma unroll 8
        for (int j = 0; j < K; j++)
            z = fmaf(Zsh[b][j], Ms[gl][j], z);   // Zsh broadcast, Ms conflict-free

        const float c  = ctl[b * G + g];
        const float tv = t[b * G + g];
        float y = coffs[b];
#pragma unroll 8
        for (int j = 0; j < HID; j++) {
            float v = fmaf(c, W1s[j],
                      fmaf(tv, W1s[HID + j],
                      fmaf(z, W1s[2 * HID + j], b1s[j])));
            y = fmaf(fmaxf(v, 0.0f), W2s[j], y);
        }
        out[b * G + g] = y;
    }
}

// ---------------------------------------------------------------------------
// metadata order: ctl, drug_targets, cell_idx, drug_fp, M, A, W1, b1,
//                 cell_emb, W2, b2   -> output [B, G] float32
// ---------------------------------------------------------------------------
extern "C" void kernel_launch(void* const* d_in, const int* in_sizes, int n_in,
                              void* d_out, int out_size)
{
    const float* ctl      = (const float*)d_in[0];
    const float* tgt      = (const float*)d_in[1];
    const int*   cell_idx = (const int*)  d_in[2];
    // d_in[3] = drug_fp (unused by the model)
    const float* M        = (const float*)d_in[4];
    const float* A        = (const float*)d_in[5];
    const float* W1       = (const float*)d_in[6];
    const float* b1       = (const float*)d_in[7];
    const float* cell_emb = (const float*)d_in[8];
    const float* W2       = (const float*)d_in[9];
    const float* b2       = (const float*)d_in[10];
    float* out = (float*)d_out;

    k1_maxpool<<<NCHUNK, 256>>>(tgt, M);
    k2_appnp<<<B, 256>>>(A, cell_idx, cell_emb, W2, b2);
    k3_out<<<(G + GT - 1) / GT, 256>>>(ctl, tgt, M, W1, b1, W2, out);
}

// round 3
// speedup vs baseline: 1.8615x; 1.8615x over previous
#include <cuda_runtime.h>

#define B 16
#define G 5000
#define K 256
#define HID 64
#define STEPS 10
#define NCHUNK 160
#define CHUNK 32      // 160*32 = 5120 >= 5000
#define GT 32         // genes per block in K3

// Scratch (no allocations allowed)
__device__ float g_partial[NCHUNK][B][K];  // 2.6 MB partial maxes
__device__ float g_Z[B][K];                // propagated module activations
__device__ float g_coff[B];                // cell_emb[cell_idx[b]] . W2 + b2

// ---------------------------------------------------------------------------
// K1: partial max-pool over a gene chunk, software-pipelined loads (MLP=8).
// t_mod_partial[chunk][b][k] = max_{g in chunk} t[b,g] * M[g,k]
// Products are nonnegative (t,M ~ uniform[0,1)), so init 0 is exact.
// ---------------------------------------------------------------------------
__global__ __launch_bounds__(256) void k1_maxpool(
    const float* __restrict__ t, const float* __restrict__ M)
{
    __shared__ float ts[B][CHUNK];
    const int tid = threadIdx.x;            // 256 threads, tid == k
    const int g0  = blockIdx.x * CHUNK;
    const int n   = min(CHUNK, G - g0);     // may be <= 0 for tail blocks

    for (int i = tid; i < B * CHUNK; i += 256) {
        int b = i >> 5, gg = i & 31;
        int g = g0 + gg;
        ts[b][gg] = (g < G) ? t[b * G + g] : 0.0f;
    }
    __syncthreads();

    float acc[B];
#pragma unroll
    for (int b = 0; b < B; b++) acc[b] = 0.0f;

    const float* Mp = M + (size_t)g0 * K + tid;

    if (n == CHUNK) {
        float pf[8], nx[8];
#pragma unroll
        for (int p = 0; p < 8; p++) pf[p] = Mp[(size_t)p * K];
#pragma unroll
        for (int grp = 0; grp < CHUNK / 8; grp++) {
            if (grp < CHUNK / 8 - 1) {
#pragma unroll
                for (int p = 0; p < 8; p++)
                    nx[p] = Mp[(size_t)(grp * 8 + 8 + p) * K];
            }
#pragma unroll
            for (int p = 0; p < 8; p++) {
                const int gg = grp * 8 + p;
                const float m = pf[p];
#pragma unroll
                for (int b = 0; b < B; b++)
                    acc[b] = fmaxf(acc[b], ts[b][gg] * m);
            }
#pragma unroll
            for (int p = 0; p < 8; p++) pf[p] = nx[p];
        }
    } else {
        for (int gg = 0; gg < n; gg++) {
            float m = Mp[(size_t)gg * K];
#pragma unroll
            for (int b = 0; b < B; b++)
                acc[b] = fmaxf(acc[b], ts[b][gg] * m);
        }
    }

#pragma unroll
    for (int b = 0; b < B; b++)
        g_partial[blockIdx.x][b][tid] = acc[b];
}

// ---------------------------------------------------------------------------
// K2: reduce partials -> t_mod, then 10-step APPNP with A fully on-chip.
// grid = 16 (one block per b), 1024 threads: thread (q = tid>>8, k = tid&255)
// owns j in [64q, 64q+64): first 32 j from smem slab, last 32 from registers.
// smem A half = rows with (j & 63) < 32, laid out slab-per-q.
// Dynamic smem: As[128][260] + Zs[256] + Ss[256] + pred[1024] = ~139 KB.
// ---------------------------------------------------------------------------
#define AS_ROW 260
#define K2_SMEM_FLOATS (128 * AS_ROW + 256 + 256 + 1024)

__global__ __launch_bounds__(1024, 1) void k2_appnp(
    const float* __restrict__ A,
    const int*   __restrict__ cell_idx,
    const float* __restrict__ cell_emb,
    const float* __restrict__ W2,
    const float* __restrict__ b2)
{
    extern __shared__ float sm[];
    float* As   = sm;                       // 128 x 260
    float* Zs   = sm + 128 * AS_ROW;        // 256
    float* Ss   = Zs + 256;                 // 256
    float* pred = Ss + 256;                 // 1024

    const int tid = threadIdx.x;
    const int b   = blockIdx.x;
    const int q   = tid >> 8;
    const int k   = tid & 255;

    // --- t_mod reduction (160 chunks, 40 per q-group) ---
    {
        float m = 0.0f;
        const float* gp = &g_partial[q * 40][b][k];
#pragma unroll 8
        for (int c = 0; c < 40; c++)
            m = fmaxf(m, gp[c * (B * K)]);
        pred[tid] = m;
    }
    __syncthreads();
    if (q == 0) {
        float v = fmaxf(fmaxf(pred[k], pred[256 + k]),
                        fmaxf(pred[512 + k], pred[768 + k]));
        Ss[k] = v;
        Zs[k] = v;
    }
    // --- cell offset: one warp ---
    if (tid >= 992) {
        int lane = tid - 992;
        int ci = cell_idx[b];
        float v = cell_emb[ci * HID + lane] * W2[lane]
                + cell_emb[ci * HID + 32 + lane] * W2[32 + lane];
#pragma unroll
        for (int o = 16; o > 0; o >>= 1)
            v += __shfl_down_sync(0xffffffffu, v, o);
        if (lane == 0) g_coff[b] = v + b2[0];
    }

    // --- register half of A: rows [64q+32, 64q+64), staged via smem slab 0 ---
    float regA[32];
#pragma unroll 1
    for (int c0 = 0; c0 < 4; c0++) {
        __syncthreads();
        for (int idx = tid; idx < 32 * 256; idx += 1024) {
            int r = idx >> 8, c = idx & 255;
            As[r * AS_ROW + c] = A[(64 * c0 + 32 + r) * K + c];
        }
        __syncthreads();
        if (q == c0) {
#pragma unroll
            for (int r = 0; r < 32; r++)
                regA[r] = As[r * AS_ROW + k];
        }
    }
    __syncthreads();

    // --- smem half of A: rows with (j&63)<32, slab l = (j>>6)*32 + (j&31) ---
    for (int idx = tid; idx < 128 * 256; idx += 1024) {
        int l = idx >> 8, c = idx & 255;
        int j = ((l >> 5) << 6) + (l & 31);
        As[l * AS_ROW + c] = A[j * K + c];
    }
    __syncthreads();

    // --- 10 APPNP steps ---
    const float* AsQ = As + (q * 32) * AS_ROW + k;
    const float* Zq  = Zs + 64 * q;
#pragma unroll 1
    for (int s = 0; s < STEPS; s++) {
        float acc0 = 0.0f, acc1 = 0.0f;
#pragma unroll
        for (int i4 = 0; i4 < 8; i4++) {
            float4 z = *(const float4*)(Zq + i4 * 4);       // broadcast
            acc0 = fmaf(AsQ[(i4 * 4 + 0) * AS_ROW], z.x, acc0);
            acc1 = fmaf(AsQ[(i4 * 4 + 1) * AS_ROW], z.y, acc1);
            acc0 = fmaf(AsQ[(i4 * 4 + 2) * AS_ROW], z.z, acc0);
            acc1 = fmaf(AsQ[(i4 * 4 + 3) * AS_ROW], z.w, acc1);
        }
#pragma unroll
        for (int i4 = 0; i4 < 8; i4++) {
            float4 z = *(const float4*)(Zq + 32 + i4 * 4);  // broadcast
            acc0 = fmaf(regA[i4 * 4 + 0], z.x, acc0);
            acc1 = fmaf(regA[i4 * 4 + 1], z.y, acc1);
            acc0 = fmaf(regA[i4 * 4 + 2], z.z, acc0);
            acc1 = fmaf(regA[i4 * 4 + 3], z.w, acc1);
        }
        pred[tid] = acc0 + acc1;
        __syncthreads();
        if (q == 0) {
            float v = pred[k] + pred[256 + k] + pred[512 + k] + pred[768 + k];
            Zs[k] = 0.9f * v + 0.1f * Ss[k];
        }
        __syncthreads();
    }

    if (q == 0) g_Z[b][k] = Zs[k];
}

// ---------------------------------------------------------------------------
// K3: fused z_gene = Z @ M^T, MLP (3->64 relu ->1), cell offset, output.
// ---------------------------------------------------------------------------
__global__ __launch_bounds__(256) void k3_out(
    const float* __restrict__ ctl,
    const float* __restrict__ t,
    const float* __restrict__ M,
    const float* __restrict__ W1,
    const float* __restrict__ b1,
    const float* __restrict__ W2,
    float* __restrict__ out)
{
    __shared__ float Ms[GT][K + 1];
    __shared__ float Zsh[B][K + 1];
    __shared__ float W1s[3 * HID];
    __shared__ float b1s[HID], W2s[HID], coffs[B];

    const int tid = threadIdx.x;        // 256
    const int g0  = blockIdx.x * GT;

    for (int i = tid; i < GT * K; i += 256) {
        int gl = i / K, j = i % K;
        int g = g0 + gl;
        Ms[gl][j] = (g < G) ? M[(size_t)g * K + j] : 0.0f;
    }
    for (int i = tid; i < B * K; i += 256)
        Zsh[i / K][i % K] = g_Z[i / K][i % K];
    if (tid < 3 * HID) W1s[tid] = W1[tid];
    if (tid < HID) { b1s[tid] = b1[tid]; W2s[tid] = W2[tid]; }
    if (tid < B)   coffs[tid] = g_coff[tid];
    __syncthreads();

    const int gl = tid & 31;
    const int g  = g0 + gl;
    if (g >= G) return;

#pragma unroll
    for (int half = 0; half < 2; half++) {
        const int b = (tid >> 5) + half * 8;

        float z = 0.0f;
#pragma unroll 8
        for (int j = 0; j < K; j++)
            z = fmaf(Zsh[b][j], Ms[gl][j], z);

        const float c  = ctl[b * G + g];
        const float tv = t[b * G + g];
        float y = coffs[b];
#pragma unroll 8
        for (int j = 0; j < HID; j++) {
            float v = fmaf(c, W1s[j],
                      fmaf(tv, W1s[HID + j],
                      fmaf(z, W1s[2 * HID + j], b1s[j])));
            y = fmaf(fmaxf(v, 0.0f), W2s[j], y);
        }
        out[b * G + g] = y;
    }
}

// ---------------------------------------------------------------------------
// metadata order: ctl, drug_targets, cell_idx, drug_fp, M, A, W1, b1,
//                 cell_emb, W2, b2   -> output [B, G] float32
// ---------------------------------------------------------------------------
extern "C" void kernel_launch(void* const* d_in, const int* in_sizes, int n_in,
                              void* d_out, int out_size)
{
    const float* ctl      = (const float*)d_in[0];
    const float* tgt      = (const float*)d_in[1];
    const int*   cell_idx = (const int*)  d_in[2];
    // d_in[3] = drug_fp (unused by the model)
    const float* M        = (const float*)d_in[4];
    const float* A        = (const float*)d_in[5];
    const float* W1       = (const float*)d_in[6];
    const float* b1       = (const float*)d_in[7];
    const float* cell_emb = (const float*)d_in[8];
    const float* W2       = (const float*)d_in[9];
    const float* b2       = (const float*)d_in[10];
    float* out = (float*)d_out;

    const int k2_smem = K2_SMEM_FLOATS * (int)sizeof(float);
    cudaFuncSetAttribute(k2_appnp,
                         cudaFuncAttributeMaxDynamicSharedMemorySize, k2_smem);

    k1_maxpool<<<NCHUNK, 256>>>(tgt, M);
    k2_appnp<<<B, 1024, k2_smem>>>(A, cell_idx, cell_emb, W2, b2);
    k3_out<<<(G + GT - 1) / GT, 256>>>(ctl, tgt, M, W1, b1, W2, out);
}

// round 4
// speedup vs baseline: 2.2309x; 1.1985x over previous
#include <cuda_runtime.h>

#define B 16
#define G 5000
#define K 256
#define HID 64
#define STEPS 10
#define NCHUNK 160
#define CHUNK 32      // 160*32 = 5120 >= 5000
#define GT 32         // genes per block in K3

// Scratch (no allocations allowed)
__device__ __align__(16) float g_partial[NCHUNK][B][K];  // 2.6 MB partial maxes
__device__ __align__(16) float g_Z[B][K];
__device__ float g_coff[B];

// ---------------------------------------------------------------------------
// K1: partial max-pool, fully vectorized.
// Thread (gr = tid>>6, q4 = tid&63): group gr handles 8 genes, k-quad 4*q4.
// All 8 gene rows prefetched as float4 (MLP=8 x 512B/warp). Group partials
// reduced in smem. Products are nonnegative, so init 0 is exact.
// ---------------------------------------------------------------------------
__global__ __launch_bounds__(256) void k1_maxpool(
    const float* __restrict__ t, const float* __restrict__ M)
{
    extern __shared__ float s1[];
    float*  ts  = s1;                       // [B][CHUNK] = 512 floats
    float4* red = (float4*)(s1 + B * CHUNK); // [4][B][64] float4

    const int tid = threadIdx.x;
    const int g0  = blockIdx.x * CHUNK;
    const int q4  = tid & 63;
    const int gr  = tid >> 6;

    for (int i = tid; i < B * CHUNK; i += 256) {
        int b = i >> 5, gg = i & 31;
        int g = g0 + gg;
        ts[b * CHUNK + gg] = (g < G) ? t[b * G + g] : 0.0f;
    }
    __syncthreads();

    float4 mv[8];
    const int gbase = g0 + gr * 8;
#pragma unroll
    for (int p = 0; p < 8; p++) {
        int g = gbase + p;
        mv[p] = (g < G) ? *(const float4*)(M + (size_t)g * K + 4 * q4)
                        : make_float4(0.f, 0.f, 0.f, 0.f);
    }

    float4 acc[B];
#pragma unroll
    for (int b = 0; b < B; b++) acc[b] = make_float4(0.f, 0.f, 0.f, 0.f);

#pragma unroll
    for (int p = 0; p < 8; p++) {
        const float4 m = mv[p];
#pragma unroll
        for (int b = 0; b < B; b++) {
            float tv = ts[b * CHUNK + gr * 8 + p];   // broadcast
            acc[b].x = fmaxf(acc[b].x, tv * m.x);
            acc[b].y = fmaxf(acc[b].y, tv * m.y);
            acc[b].z = fmaxf(acc[b].z, tv * m.z);
            acc[b].w = fmaxf(acc[b].w, tv * m.w);
        }
    }

#pragma unroll
    for (int b = 0; b < B; b++)
        red[(gr * B + b) * 64 + q4] = acc[b];
    __syncthreads();

    for (int i = tid; i < B * 64; i += 256) {
        int b = i >> 6, qq = i & 63;
        float4 a0 = red[(0 * B + b) * 64 + qq];
        float4 a1 = red[(1 * B + b) * 64 + qq];
        float4 a2 = red[(2 * B + b) * 64 + qq];
        float4 a3 = red[(3 * B + b) * 64 + qq];
        float4 r;
        r.x = fmaxf(fmaxf(a0.x, a1.x), fmaxf(a2.x, a3.x));
        r.y = fmaxf(fmaxf(a0.y, a1.y), fmaxf(a2.y, a3.y));
        r.z = fmaxf(fmaxf(a0.z, a1.z), fmaxf(a2.z, a3.z));
        r.w = fmaxf(fmaxf(a0.w, a1.w), fmaxf(a2.w, a3.w));
        *(float4*)(&g_partial[blockIdx.x][b][4 * qq]) = r;
    }
}
#define K1_SMEM_BYTES ((B * CHUNK + 4 * B * 64 * 4) * (int)sizeof(float))

// ---------------------------------------------------------------------------
// K2: reduce partials -> t_mod, then 10-step APPNP with A fully on-chip.
// grid = 16 (one block per b), 1024 threads: thread (q = tid>>8, k = tid&255)
// owns j in [64q, 64q+64): 32 from smem slab + 32 from registers.
// All global<->smem staging float4-vectorized.
// ---------------------------------------------------------------------------
#define AS_ROW 260
#define K2_SMEM_FLOATS (128 * AS_ROW + 256 + 256 + 1024)

__global__ __launch_bounds__(1024, 1) void k2_appnp(
    const float* __restrict__ A,
    const int*   __restrict__ cell_idx,
    const float* __restrict__ cell_emb,
    const float* __restrict__ W2,
    const float* __restrict__ b2)
{
    extern __shared__ float sm[];
    float* As   = sm;                       // 128 x 260
    float* Zs   = sm + 128 * AS_ROW;        // 256
    float* Ss   = Zs + 256;                 // 256
    float* pred = Ss + 256;                 // 1024

    const int tid = threadIdx.x;
    const int b   = blockIdx.x;
    const int q   = tid >> 8;
    const int k   = tid & 255;

    // --- t_mod reduction (160 chunks, 40 per q-group) ---
    {
        float m = 0.0f;
        const float* gp = &g_partial[q * 40][b][k];
#pragma unroll 8
        for (int c = 0; c < 40; c++)
            m = fmaxf(m, gp[c * (B * K)]);
        pred[tid] = m;
    }
    __syncthreads();
    if (q == 0) {
        float v = fmaxf(fmaxf(pred[k], pred[256 + k]),
                        fmaxf(pred[512 + k], pred[768 + k]));
        Ss[k] = v;
        Zs[k] = v;
    }
    // --- cell offset: one warp ---
    if (tid >= 992) {
        int lane = tid - 992;
        int ci = cell_idx[b];
        float v = cell_emb[ci * HID + lane] * W2[lane]
                + cell_emb[ci * HID + 32 + lane] * W2[32 + lane];
#pragma unroll
        for (int o = 16; o > 0; o >>= 1)
            v += __shfl_down_sync(0xffffffffu, v, o);
        if (lane == 0) g_coff[b] = v + b2[0];
    }

    // --- register half of A: rows [64q+32, 64q+64), staged via smem slab 0 ---
    float regA[32];
#pragma unroll 1
    for (int c0 = 0; c0 < 4; c0++) {
        __syncthreads();
        for (int idx = tid; idx < 32 * 64; idx += 1024) {
            int r = idx >> 6, cq = idx & 63;
            *(float4*)(As + r * AS_ROW + 4 * cq) =
                *(const float4*)(A + (64 * c0 + 32 + r) * K + 4 * cq);
        }
        __syncthreads();
        if (q == c0) {
#pragma unroll
            for (int r = 0; r < 32; r++)
                regA[r] = As[r * AS_ROW + k];
        }
    }
    __syncthreads();

    // --- smem half of A: rows with (j&63)<32, slab l = (j>>6)*32 + (j&31) ---
    for (int idx = tid; idx < 128 * 64; idx += 1024) {
        int l = idx >> 6, cq = idx & 63;
        int j = ((l >> 5) << 6) + (l & 31);
        *(float4*)(As + l * AS_ROW + 4 * cq) =
            *(const float4*)(A + j * K + 4 * cq);
    }
    __syncthreads();

    // --- 10 APPNP steps ---
    const float* AsQ = As + (q * 32) * AS_ROW + k;
    const float* Zq  = Zs + 64 * q;
#pragma unroll 1
    for (int s = 0; s < STEPS; s++) {
        float acc0 = 0.0f, acc1 = 0.0f;
#pragma unroll
        for (int i4 = 0; i4 < 8; i4++) {
            float4 z = *(const float4*)(Zq + i4 * 4);       // broadcast
            acc0 = fmaf(AsQ[(i4 * 4 + 0) * AS_ROW], z.x, acc0);
            acc1 = fmaf(AsQ[(i4 * 4 + 1) * AS_ROW], z.y, acc1);
            acc0 = fmaf(AsQ[(i4 * 4 + 2) * AS_ROW], z.z, acc0);
            acc1 = fmaf(AsQ[(i4 * 4 + 3) * AS_ROW], z.w, acc1);
        }
#pragma unroll
        for (int i4 = 0; i4 < 8; i4++) {
            float4 z = *(const float4*)(Zq + 32 + i4 * 4);  // broadcast
            acc0 = fmaf(regA[i4 * 4 + 0], z.x, acc0);
            acc1 = fmaf(regA[i4 * 4 + 1], z.y, acc1);
            acc0 = fmaf(regA[i4 * 4 + 2], z.z, acc0);
            acc1 = fmaf(regA[i4 * 4 + 3], z.w, acc1);
        }
        pred[tid] = acc0 + acc1;
        __syncthreads();
        if (q == 0) {
            float v = pred[k] + pred[256 + k] + pred[512 + k] + pred[768 + k];
            Zs[k] = 0.9f * v + 0.1f * Ss[k];
        }
        __syncthreads();
    }

    if (q == 0) g_Z[b][k] = Zs[k];
}

// ---------------------------------------------------------------------------
// K3: fused z_gene = Z @ M^T + MLP + output.
// Warp w = b-pair (w, w+8); lane = gene. Ms padded to 257 so the per-lane
// column access (stride 257) is bank-conflict-free; each M element serves
// both b of the pair. Z pre-packed as float2[j][w].
// ---------------------------------------------------------------------------
__global__ __launch_bounds__(256) void k3_out(
    const float* __restrict__ ctl,
    const float* __restrict__ t,
    const float* __restrict__ M,
    const float* __restrict__ W1,
    const float* __restrict__ b1,
    const float* __restrict__ W2,
    float* __restrict__ out)
{
    extern __shared__ float s3[];
    float*  Ms   = s3;                         // GT * 257
    float2* Zp   = (float2*)(s3 + GT * 257);   // [K][8] pairs
    float*  W1s  = s3 + GT * 257 + K * 8 * 2;
    float*  b1s  = W1s + 3 * HID;
    float*  W2s  = b1s + HID;
    float*  coffs= W2s + HID;

    const int tid = threadIdx.x;
    const int g0  = blockIdx.x * GT;

    // Stage M tile: coalesced float4 loads (L2-resident), scalar stores.
    for (int i = tid; i < GT * 64; i += 256) {
        int gl = i >> 6, jq = i & 63;
        int g = g0 + gl;
        float4 v = (g < G) ? *(const float4*)(M + (size_t)g * K + 4 * jq)
                           : make_float4(0.f, 0.f, 0.f, 0.f);
        float* d = Ms + gl * 257 + 4 * jq;
        d[0] = v.x; d[1] = v.y; d[2] = v.z; d[3] = v.w;
    }
    // Stage Z pairs
    for (int i = tid; i < K * 8; i += 256) {
        int j = i >> 3, w = i & 7;
        Zp[i] = make_float2(g_Z[w][j], g_Z[w + 8][j]);
    }
    if (tid < 3 * HID) W1s[tid] = W1[tid];
    if (tid < HID) { b1s[tid] = b1[tid]; W2s[tid] = W2[tid]; }
    if (tid < B)   coffs[tid] = g_coff[tid];
    __syncthreads();

    const int gl = tid & 31;
    const int w  = tid >> 5;            // b-pair index
    const int g  = g0 + gl;
    if (g >= G) return;

    float z0 = 0.0f, z1 = 0.0f;
    const float*  Mrow = Ms + gl * 257;
    const float2* Zw   = Zp + w;
#pragma unroll 8
    for (int j = 0; j < K; j++) {
        float  m  = Mrow[j];            // conflict-free column across lanes
        float2 zz = Zw[j * 8];          // broadcast within warp
        z0 = fmaf(zz.x, m, z0);
        z1 = fmaf(zz.y, m, z1);
    }

    const float c0 = ctl[w * G + g],        c1 = ctl[(w + 8) * G + g];
    const float t0 = t[w * G + g],          t1 = t[(w + 8) * G + g];
    float y0 = coffs[w], y1 = coffs[w + 8];
#pragma unroll 8
    for (int j = 0; j < HID; j++) {
        float w1c = W1s[j], w1t = W1s[HID + j], w1z = W1s[2 * HID + j];
        float bb  = b1s[j], w2 = W2s[j];
        float v0 = fmaf(c0, w1c, fmaf(t0, w1t, fmaf(z0, w1z, bb)));
        float v1 = fmaf(c1, w1c, fmaf(t1, w1t, fmaf(z1, w1z, bb)));
        y0 = fmaf(fmaxf(v0, 0.0f), w2, y0);
        y1 = fmaf(fmaxf(v1, 0.0f), w2, y1);
    }
    out[w * G + g] = y0;
    out[(w + 8) * G + g] = y1;
}
#define K3_SMEM_BYTES ((GT * 257 + K * 8 * 2 + 3 * HID + HID + HID + B) * (int)sizeof(float))

// ---------------------------------------------------------------------------
// metadata order: ctl, drug_targets, cell_idx, drug_fp, M, A, W1, b1,
//                 cell_emb, W2, b2   -> output [B, G] float32
// ---------------------------------------------------------------------------
extern "C" void kernel_launch(void* const* d_in, const int* in_sizes, int n_in,
                              void* d_out, int out_size)
{
    const float* ctl      = (const float*)d_in[0];
    const float* tgt      = (const float*)d_in[1];
    const int*   cell_idx = (const int*)  d_in[2];
    // d_in[3] = drug_fp (unused by the model)
    const float* M        = (const float*)d_in[4];
    const float* A        = (const float*)d_in[5];
    const float* W1       = (const float*)d_in[6];
    const float* b1       = (const float*)d_in[7];
    const float* cell_emb = (const float*)d_in[8];
    const float* W2       = (const float*)d_in[9];
    const float* b2       = (const float*)d_in[10];
    float* out = (float*)d_out;

    const int k2_smem = K2_SMEM_FLOATS * (int)sizeof(float);
    cudaFuncSetAttribute(k1_maxpool,
                         cudaFuncAttributeMaxDynamicSharedMemorySize, K1_SMEM_BYTES);
    cudaFuncSetAttribute(k2_appnp,
                         cudaFuncAttributeMaxDynamicSharedMemorySize, k2_smem);
    cudaFuncSetAttribute(k3_out,
                         cudaFuncAttributeMaxDynamicSharedMemorySize, K3_SMEM_BYTES);

    k1_maxpool<<<NCHUNK, 256, K1_SMEM_BYTES>>>(tgt, M);
    k2_appnp<<<B, 1024, k2_smem>>>(A, cell_idx, cell_emb, W2, b2);
    k3_out<<<(G + GT - 1) / GT, 256, K3_SMEM_BYTES>>>(ctl, tgt, M, W1, b1, W2, out);
}